// round 13
// baseline (speedup 1.0000x reference)
#include <cuda_runtime.h>
#include <cuda_fp16.h>
#include <math.h>
#include <cstdint>

typedef unsigned long long u64;

// ==================== scratch ====================
__device__ __align__(128) __half g_ah[2048 * 4096];        // fp16(x) / A for QKV
__device__ __align__(128) __half g_aout_h[2048 * 4096];    // fp16 attn out / A for out-proj
__device__ __align__(128) __half g_qh[64 * 1024 * 128];
__device__ __align__(128) __half g_ql[64 * 1024 * 128];
__device__ __align__(128) __half g_kh[64 * 1024 * 128];
__device__ __align__(128) __half g_kl[64 * 1024 * 128];
__device__ __align__(128) __half g_vh[64 * 1024 * 128];
__device__ __align__(128) __half g_bqkv[12288 * 4096];     // [N,K] fp16
__device__ __align__(128) __half g_wout[4096 * 4096];      // [N,K] fp16

// ==================== PTX helpers ====================
__device__ __forceinline__ uint32_t smem_u32(const void* p) {
    uint32_t a;
    asm("{ .reg .u64 t; cvta.to.shared.u64 t, %1; cvt.u32.u64 %0, t; }" : "=r"(a) : "l"(p));
    return a;
}
__device__ __forceinline__ uint32_t h2_as_u32(__half2 h) {
    union { __half2 h2; uint32_t u; } cvt;
    cvt.h2 = h;
    return cvt.u;
}
__device__ __forceinline__ __half2 u32_as_h2(uint32_t u) {
    union { uint32_t u; __half2 h2; } cvt;
    cvt.u = u;
    return cvt.h2;
}
__device__ __forceinline__ void cp16(uint32_t dst, const void* src) {
    asm volatile("cp.async.cg.shared.global [%0], [%1], 16;" :: "r"(dst), "l"(src));
}
__device__ __forceinline__ void cp_commit() { asm volatile("cp.async.commit_group;" ::: "memory"); }
template <int N> __device__ __forceinline__ void cp_wait() { asm volatile("cp.async.wait_group %0;" :: "n"(N) : "memory"); }

#define LDSM_X4(r0, r1, r2, r3, addr) \
    asm volatile("ldmatrix.sync.aligned.m8n8.x4.shared.b16 {%0,%1,%2,%3}, [%4];" \
        : "=r"(r0), "=r"(r1), "=r"(r2), "=r"(r3) : "r"(addr))
#define LDSM_X4_T(r0, r1, r2, r3, addr) \
    asm volatile("ldmatrix.sync.aligned.m8n8.x4.trans.shared.b16 {%0,%1,%2,%3}, [%4];" \
        : "=r"(r0), "=r"(r1), "=r"(r2), "=r"(r3) : "r"(addr))

#define MMA16816(d, a0, a1, a2, a3, b0, b1) \
    asm volatile("mma.sync.aligned.m16n8k16.row.col.f32.f16.f16.f32 " \
        "{%0,%1,%2,%3},{%4,%5,%6,%7},{%8,%9},{%0,%1,%2,%3};" \
        : "+f"((d)[0]), "+f"((d)[1]), "+f"((d)[2]), "+f"((d)[3]) \
        : "r"(a0), "r"(a1), "r"(a2), "r"(a3), "r"(b0), "r"(b1))

#define SMEM_SWZ(off)    ((off) ^ (((off) >> 3) & 0x70))   // 128B rows
#define SMEM_SWZ256(off) ((off) ^ (((off) >> 4) & 0x70))   // 256B rows

// ==================== prep kernels ====================
__global__ void __launch_bounds__(256) convert_h_kernel(const float* __restrict__ in,
                                                        __half* __restrict__ out) {
    const size_t i = (size_t)blockIdx.x * 256 + threadIdx.x;
    float4 v = ((const float4*)in)[i];
    __half2* op = (__half2*)out;
    op[2 * i]     = __floats2half2_rn(v.x, v.y);
    op[2 * i + 1] = __floats2half2_rn(v.z, v.w);
}

// W: [K,N] fp32 -> [N,K] fp16, half2 stores. block (32,8), tile 64k x 32n.
__global__ void __launch_bounds__(256) splitT_kernel(const float* __restrict__ in,
                                                     __half* __restrict__ outT, int K, int N) {
    __shared__ float t[64][33];
    const int n0 = blockIdx.x * 32, k0 = blockIdx.y * 64;
    const int tx = threadIdx.x, ty = threadIdx.y;
    #pragma unroll
    for (int i = ty; i < 64; i += 8)
        t[i][tx] = in[(size_t)(k0 + i) * N + n0 + tx];
    __syncthreads();
    #pragma unroll
    for (int i = ty; i < 32; i += 8) {
        const __half2 hv = __floats2half2_rn(t[tx * 2][i], t[tx * 2 + 1][i]);
        *(__half2*)(outT + (size_t)(n0 + i) * K + k0 + tx * 2) = hv;
    }
}

// ==================== HMMA GEMM (CTA 128x128, warp 64x32, 2 CTAs/SM) ====================
#define STG_BYTES 32768          // 16KB A + 16KB B
#define GEMM_SMEM (3 * STG_BYTES)

__device__ __forceinline__ void gemm_load_stage(
    const __half* __restrict__ A, const __half* __restrict__ Bt,
    int bm, int bn, int K, int kk, uint32_t stg, int tid)
{
    #pragma unroll
    for (int i = 0; i < 4; i++) {
        const int ch = tid + i * 256;
        const int r = ch >> 3, cc = ch & 7;
        cp16(stg + SMEM_SWZ((uint32_t)(r * 128 + cc * 16)),
             A + (size_t)(bm + r) * K + kk + cc * 8);
    }
    #pragma unroll
    for (int i = 0; i < 4; i++) {
        const int ch = tid + i * 256;
        const int r = ch >> 3, cc = ch & 7;
        cp16(stg + 16384 + SMEM_SWZ((uint32_t)(r * 128 + cc * 16)),
             Bt + (size_t)(bn + r) * K + kk + cc * 8);
    }
}

__device__ __forceinline__ void store_qkv_elem(int row, int col, float a, float b,
                                               float* __restrict__ outK, float* __restrict__ outV) {
    const int bb = row >> 10, s = row & 1023;
    const int seg = col >> 12, w = col & 4095;
    const int h = w >> 7, dd = w & 127;
    const int bh = bb * 32 + h;
    const __half ha = __float2half_rn(a), hb = __float2half_rn(b);
    const __half2 hh = __halves2half2(ha, hb);
    const size_t i16 = ((size_t)bh * 1024 + s) * 128 + dd;
    if (seg == 0) {
        const __half la = __float2half_rn(a - __half2float(ha));
        const __half lb = __float2half_rn(b - __half2float(hb));
        *(__half2*)(g_qh + i16) = hh;
        *(__half2*)(g_ql + i16) = __halves2half2(la, lb);
    } else if (seg == 1) {
        const __half la = __float2half_rn(a - __half2float(ha));
        const __half lb = __float2half_rn(b - __half2float(hb));
        *(float2*)(outK + ((size_t)bh * 2048 + s) * 128 + dd) = float2{a, b};
        *(__half2*)(g_kh + i16) = hh;
        *(__half2*)(g_kl + i16) = __halves2half2(la, lb);
    } else {
        *(float2*)(outV + ((size_t)bh * 2048 + s) * 128 + dd) = float2{a, b};
        *(__half2*)(g_vh + i16) = hh;
    }
}

template <int MODE>
__global__ void __launch_bounds__(256, 2) gemm_hmma(
    const __half* __restrict__ A, const __half* __restrict__ Bt,
    const float* __restrict__ bias, int N, int K, int bm0,
    float* __restrict__ out0, float* __restrict__ outK, float* __restrict__ outV)
{
    extern __shared__ char smem[];
    const uint32_t sb = smem_u32(smem);
    const int tid = threadIdx.x;
    const int bm = blockIdx.x * 128 + bm0;
    const int bn = blockIdx.y * 128;
    const int wid = tid >> 5, lane = tid & 31;
    const int wm = (wid & 1) * 64;
    const int wn = (wid >> 1) * 32;

    const int arow = wm + (lane & 15);
    const int achb = lane >> 4;
    const int brow = wn + (lane & 7) + ((lane & 16) >> 1);
    const int bchb = (lane >> 3) & 1;

    float acc[4][4][4];
    #pragma unroll
    for (int i = 0; i < 4; i++)
        #pragma unroll
        for (int j = 0; j < 4; j++)
            #pragma unroll
            for (int e = 0; e < 4; e++) acc[i][j][e] = 0.f;

    const int T = K >> 6;

    #pragma unroll
    for (int s = 0; s < 2; s++) {
        gemm_load_stage(A, Bt, bm, bn, K, s * 64, sb + s * STG_BYTES, tid);
        cp_commit();
    }

    for (int kt = 0; kt < T; kt++) {
        if (kt < T - 2) cp_wait<1>(); else cp_wait<0>();
        __syncthreads();

        if (kt + 2 < T) {
            gemm_load_stage(A, Bt, bm, bn, K, (kt + 2) * 64,
                            sb + ((kt + 2) % 3) * STG_BYTES, tid);
            cp_commit();
        }

        const uint32_t stg = sb + (kt % 3) * STG_BYTES;
        const uint32_t Ab = stg, Bb = stg + 16384;

        #pragma unroll
        for (int ks = 0; ks < 4; ks++) {
            uint32_t bfr[4][2];
            #pragma unroll
            for (int j2 = 0; j2 < 2; j2++) {
                const int rr = brow + j2 * 16;
                const int ch = (ks * 2 + bchb) ^ (rr & 7);
                uint32_t r0, r1, r2, r3;
                LDSM_X4(r0, r1, r2, r3, Bb + (uint32_t)(rr * 128 + ch * 16));
                bfr[j2 * 2 + 0][0] = r0; bfr[j2 * 2 + 0][1] = r1;
                bfr[j2 * 2 + 1][0] = r2; bfr[j2 * 2 + 1][1] = r3;
            }
            #pragma unroll
            for (int i = 0; i < 4; i++) {
                const int rr = arow + i * 16;
                const int ch = (ks * 2 + achb) ^ (rr & 7);
                uint32_t a0, a1, a2, a3;
                LDSM_X4(a0, a1, a2, a3, Ab + (uint32_t)(rr * 128 + ch * 16));
                #pragma unroll
                for (int j = 0; j < 4; j++)
                    MMA16816(acc[i][j], a0, a1, a2, a3, bfr[j][0], bfr[j][1]);
            }
        }
    }

    // epilogue
    const int lr = lane >> 2, lc2 = (lane & 3) * 2;
    #pragma unroll
    for (int i = 0; i < 4; i++) {
        #pragma unroll
        for (int j = 0; j < 4; j++) {
            const int c = bn + wn + j * 8 + lc2;
            const float bx = __ldg(bias + c);
            const float by = __ldg(bias + c + 1);
            const int r0 = bm + wm + i * 16 + lr;
            const float v0 = acc[i][j][0] + bx, v1 = acc[i][j][1] + by;
            const float v2 = acc[i][j][2] + bx, v3 = acc[i][j][3] + by;
            if (MODE == 0) {
                *(float2*)(out0 + (size_t)r0 * N + c) = float2{v0, v1};
                *(float2*)(out0 + (size_t)(r0 + 8) * N + c) = float2{v2, v3};
            } else {
                store_qkv_elem(r0, c, v0, v1, outK, outV);
                store_qkv_elem(r0 + 8, c, v2, v3, outK, outV);
            }
        }
    }
}

// ==================== HMMA flash attention (64 q-rows, 4 warps, 2 CTAs/SM) ====================
// QK = qh*kh + ql*kh + qh*kl ; PV = ph*vh (denominator from rounded ph).
// Operand-phased single buffers: K(t+1) loads during softmax/PV; V(t+1) during next QK.
#define ATT_QH 0
#define ATT_QL 16384
#define ATT_KH 32768
#define ATT_KL 49152
#define ATT_VH 65536
#define ATT_SMEM 81920

__device__ __forceinline__ void attn_load_tile128(uint32_t dst, const __half* __restrict__ src,
                                                  int tid) {
    // 64 rows x 128 halves (256B rows, swizzled), 128 threads
    #pragma unroll
    for (int i = 0; i < 8; i++) {
        const int ch = tid + i * 128;
        const int r = ch >> 4, c = ch & 15;
        cp16(dst + SMEM_SWZ256((uint32_t)(r * 256 + c * 16)), src + (size_t)r * 128 + c * 8);
    }
}

__global__ void __launch_bounds__(128, 2) attn_hmma(int bh0)
{
    extern __shared__ char smem[];
    const uint32_t sb = smem_u32(smem);
    const int qt = (int)gridDim.x - 1 - (int)blockIdx.x;   // longest-first schedule
    const int bh = blockIdx.y + bh0;
    const int b = bh >> 5, h = bh & 31;
    const int tid = threadIdx.x;
    const int wid = tid >> 5, lane = tid & 31;

    // Q tiles (group: Qh+Ql)
    const size_t qoff = ((size_t)bh * 1024 + qt * 64) * 128;
    attn_load_tile128(sb + ATT_QH, g_qh + qoff, tid);
    attn_load_tile128(sb + ATT_QL, g_ql + qoff, tid);
    cp_commit();

    const int nkt = qt + 1;
    const size_t kvbase = (size_t)bh * 1024 * 128;

    // prologue: K0 group, V0 group
    attn_load_tile128(sb + ATT_KH, g_kh + kvbase, tid);
    attn_load_tile128(sb + ATT_KL, g_kl + kvbase, tid);
    cp_commit();
    attn_load_tile128(sb + ATT_VH, g_vh + kvbase, tid);
    cp_commit();

    float o[16][4];
    #pragma unroll
    for (int nt = 0; nt < 16; nt++)
        #pragma unroll
        for (int e = 0; e < 4; e++) o[nt][e] = 0.f;
    float m1 = -INFINITY, m2 = -INFINITY, l1 = 0.f, l2 = 0.f;
    const float scale2 = 0.08838834764831845f * 1.4426950408889634f;  // scale*log2(e)

    const int row1 = qt * 64 + wid * 16 + (lane >> 2);
    const int row2 = row1 + 8;

    const int qar = wid * 16 + (lane & 15);
    const int qchb = lane >> 4;
    const int kbr = (lane & 7) + ((lane & 16) >> 1);
    const int kchb = (lane >> 3) & 1;
    const int vkv = lane & 15;
    const int vdc = lane >> 4;

    for (int kt = 0; kt < nkt; kt++) {
        // wait: Q + K_kt complete (V_kt may still be in flight)
        cp_wait<1>();
        __syncthreads();

        float s[8][4];
        #pragma unroll
        for (int nt = 0; nt < 8; nt++)
            #pragma unroll
            for (int e = 0; e < 4; e++) s[nt][e] = 0.f;

        // QK pass 1+2: (qh+ql) * kh
        #pragma unroll
        for (int ks = 0; ks < 8; ks++) {
            uint32_t bfr[8][2];
            #pragma unroll
            for (int j2 = 0; j2 < 4; j2++) {
                const int rr = kbr + j2 * 16;
                const int ch = (ks * 2 + kchb) ^ (lane & 7);
                uint32_t r0, r1, r2, r3;
                LDSM_X4(r0, r1, r2, r3, sb + ATT_KH + (uint32_t)(rr * 256 + ch * 16));
                bfr[j2 * 2][0] = r0; bfr[j2 * 2][1] = r1;
                bfr[j2 * 2 + 1][0] = r2; bfr[j2 * 2 + 1][1] = r3;
            }
            const int ch = (ks * 2 + qchb) ^ (qar & 7);
            uint32_t a0, a1, a2, a3;
            LDSM_X4(a0, a1, a2, a3, sb + ATT_QH + (uint32_t)(qar * 256 + ch * 16));
            #pragma unroll
            for (int j = 0; j < 8; j++) MMA16816(s[j], a0, a1, a2, a3, bfr[j][0], bfr[j][1]);
            LDSM_X4(a0, a1, a2, a3, sb + ATT_QL + (uint32_t)(qar * 256 + ch * 16));
            #pragma unroll
            for (int j = 0; j < 8; j++) MMA16816(s[j], a0, a1, a2, a3, bfr[j][0], bfr[j][1]);
        }
        // QK pass 3: qh * kl
        #pragma unroll
        for (int ks = 0; ks < 8; ks++) {
            uint32_t bfr[8][2];
            #pragma unroll
            for (int j2 = 0; j2 < 4; j2++) {
                const int rr = kbr + j2 * 16;
                const int ch = (ks * 2 + kchb) ^ (lane & 7);
                uint32_t r0, r1, r2, r3;
                LDSM_X4(r0, r1, r2, r3, sb + ATT_KL + (uint32_t)(rr * 256 + ch * 16));
                bfr[j2 * 2][0] = r0; bfr[j2 * 2][1] = r1;
                bfr[j2 * 2 + 1][0] = r2; bfr[j2 * 2 + 1][1] = r3;
            }
            const int ch = (ks * 2 + qchb) ^ (qar & 7);
            uint32_t a0, a1, a2, a3;
            LDSM_X4(a0, a1, a2, a3, sb + ATT_QH + (uint32_t)(qar * 256 + ch * 16));
            #pragma unroll
            for (int j = 0; j < 8; j++) MMA16816(s[j], a0, a1, a2, a3, bfr[j][0], bfr[j][1]);
        }

        // K buffers free -> start K(t+1) load
        __syncthreads();
        if (kt + 1 < nkt) {
            const size_t off = kvbase + (size_t)(kt + 1) * 64 * 128;
            attn_load_tile128(sb + ATT_KH, g_kh + off, tid);
            attn_load_tile128(sb + ATT_KL, g_kl + off, tid);
            cp_commit();
        }

        // scale (base-2) + mask (diagonal tile only) + online softmax
        const bool need_mask = (kt == qt);
        float mx1 = -INFINITY, mx2 = -INFINITY;
        #pragma unroll
        for (int nt = 0; nt < 8; nt++) {
            const int cg = kt * 64 + nt * 8 + (lane & 3) * 2;
            #pragma unroll
            for (int e = 0; e < 2; e++) {
                float v = s[nt][e] * scale2;
                if (need_mask && (cg + e > row1)) v = -INFINITY;
                s[nt][e] = v; mx1 = fmaxf(mx1, v);
            }
            #pragma unroll
            for (int e = 2; e < 4; e++) {
                float v = s[nt][e] * scale2;
                if (need_mask && (cg + e - 2 > row2)) v = -INFINITY;
                s[nt][e] = v; mx2 = fmaxf(mx2, v);
            }
        }
        mx1 = fmaxf(mx1, __shfl_xor_sync(0xffffffffu, mx1, 1));
        mx1 = fmaxf(mx1, __shfl_xor_sync(0xffffffffu, mx1, 2));
        mx2 = fmaxf(mx2, __shfl_xor_sync(0xffffffffu, mx2, 1));
        mx2 = fmaxf(mx2, __shfl_xor_sync(0xffffffffu, mx2, 2));
        const float mn1 = fmaxf(m1, mx1), mn2 = fmaxf(m2, mx2);
        const float c1 = exp2f(m1 - mn1), c2 = exp2f(m2 - mn2);
        m1 = mn1; m2 = mn2;

        uint32_t ph2[8][2];
        float ts1 = 0.f, ts2 = 0.f;
        #pragma unroll
        for (int nt = 0; nt < 8; nt++) {
            const uint32_t u1 = h2_as_u32(__floats2half2_rn(s[nt][0] - mn1, s[nt][1] - mn1));
            const uint32_t u2 = h2_as_u32(__floats2half2_rn(s[nt][2] - mn2, s[nt][3] - mn2));
            uint32_t r1u, r2u;
            asm("ex2.approx.f16x2 %0, %1;" : "=r"(r1u) : "r"(u1));
            asm("ex2.approx.f16x2 %0, %1;" : "=r"(r2u) : "r"(u2));
            ph2[nt][0] = r1u; ph2[nt][1] = r2u;
            const float2 f1 = __half22float2(u32_as_h2(r1u));
            const float2 f2 = __half22float2(u32_as_h2(r2u));
            ts1 += f1.x + f1.y;
            ts2 += f2.x + f2.y;
        }
        l1 = l1 * c1 + ts1; l2 = l2 * c2 + ts2;
        #pragma unroll
        for (int nt = 0; nt < 16; nt++) {
            o[nt][0] *= c1; o[nt][1] *= c1; o[nt][2] *= c2; o[nt][3] *= c2;
        }

        // wait: V_kt complete (K(t+1) may be pending)
        if (kt + 1 < nkt) cp_wait<1>(); else cp_wait<0>();
        __syncthreads();

        // PV: ph * vh
        #pragma unroll
        for (int ks = 0; ks < 4; ks++) {
            const uint32_t ah0 = ph2[2 * ks][0], ah1 = ph2[2 * ks][1];
            const uint32_t ah2 = ph2[2 * ks + 1][0], ah3 = ph2[2 * ks + 1][1];
            #pragma unroll
            for (int d2 = 0; d2 < 8; d2++) {
                const int kvr = ks * 16 + vkv;
                const int ch = (d2 * 2 + vdc) ^ (vkv & 7);
                const uint32_t va = (uint32_t)(kvr * 256 + ch * 16);
                uint32_t v0, v1, v2, v3;
                LDSM_X4_T(v0, v1, v2, v3, sb + ATT_VH + va);
                MMA16816(o[2 * d2],     ah0, ah1, ah2, ah3, v0, v1);
                MMA16816(o[2 * d2 + 1], ah0, ah1, ah2, ah3, v2, v3);
            }
        }

        // V buffer free -> start V(t+1) load
        __syncthreads();
        if (kt + 1 < nkt) {
            attn_load_tile128(sb + ATT_VH, g_vh + kvbase + (size_t)(kt + 1) * 64 * 128, tid);
            cp_commit();
        }
    }

    l1 += __shfl_xor_sync(0xffffffffu, l1, 1);
    l1 += __shfl_xor_sync(0xffffffffu, l1, 2);
    l2 += __shfl_xor_sync(0xffffffffu, l2, 1);
    l2 += __shfl_xor_sync(0xffffffffu, l2, 2);
    const float i1 = 1.f / l1, i2 = 1.f / l2;

    __half* outp = g_aout_h;
    #pragma unroll
    for (int nt = 0; nt < 16; nt++) {
        const int col = h * 128 + nt * 8 + (lane & 3) * 2;
        *(__half2*)(outp + (size_t)(b * 1024 + row1) * 4096 + col) =
            __floats2half2_rn(o[nt][0] * i1, o[nt][1] * i1);
        *(__half2*)(outp + (size_t)(b * 1024 + row2) * 4096 + col) =
            __floats2half2_rn(o[nt][2] * i2, o[nt][3] * i2);
    }
}

// ==================== launch ====================
extern "C" void kernel_launch(void* const* d_in, const int* in_sizes, int n_in,
                              void* d_out, int out_size)
{
    const float* x       = (const float*)d_in[0];
    const float* W_qkv   = (const float*)d_in[2];
    const float* b_qkv   = (const float*)d_in[3];
    const float* W_out   = (const float*)d_in[4];
    const float* b_out   = (const float*)d_in[5];
    const float* cache_k = (const float*)d_in[6];
    const float* cache_v = (const float*)d_in[7];

    float* out  = (float*)d_out;
    float* y    = out;
    float* outK = out + 8388608;
    float* outV = out + 25165824;

    __half *ah, *aout, *bq, *wo;
    cudaGetSymbolAddress((void**)&ah, g_ah);
    cudaGetSymbolAddress((void**)&aout, g_aout_h);
    cudaGetSymbolAddress((void**)&bq, g_bqkv);
    cudaGetSymbolAddress((void**)&wo, g_wout);

    // one-time side-stream + fork/join events (no device memory involved)
    static cudaStream_t s1 = nullptr;
    static cudaEvent_t evFork = nullptr, evConv = nullptr, evPrep = nullptr;
    static cudaEvent_t evQKV = nullptr, evA0 = nullptr, evDone1 = nullptr;
    if (s1 == nullptr) {
        cudaStreamCreateWithFlags(&s1, cudaStreamNonBlocking);
        cudaEventCreateWithFlags(&evFork, cudaEventDisableTiming);
        cudaEventCreateWithFlags(&evConv, cudaEventDisableTiming);
        cudaEventCreateWithFlags(&evPrep, cudaEventDisableTiming);
        cudaEventCreateWithFlags(&evQKV, cudaEventDisableTiming);
        cudaEventCreateWithFlags(&evA0, cudaEventDisableTiming);
        cudaEventCreateWithFlags(&evDone1, cudaEventDisableTiming);
    }

    cudaFuncSetAttribute(gemm_hmma<0>, cudaFuncAttributeMaxDynamicSharedMemorySize, GEMM_SMEM);
    cudaFuncSetAttribute(gemm_hmma<1>, cudaFuncAttributeMaxDynamicSharedMemorySize, GEMM_SMEM);
    cudaFuncSetAttribute(attn_hmma, cudaFuncAttributeMaxDynamicSharedMemorySize, ATT_SMEM);

    // ---- fork side stream ----
    cudaEventRecord(evFork, 0);
    cudaStreamWaitEvent(s1, evFork, 0);

    // side stream: x->fp16, cache tail copies, W_out transpose
    convert_h_kernel<<<8192, 256, 0, s1>>>(x, ah);
    cudaEventRecord(evConv, s1);
    {
        const size_t pitch = (size_t)2048 * 128 * sizeof(float);
        const size_t width = (size_t)1024 * 128 * sizeof(float);
        cudaMemcpy2DAsync(outK + (size_t)1024 * 128, pitch,
                          cache_k + (size_t)1024 * 128, pitch, width, 64,
                          cudaMemcpyDeviceToDevice, s1);
        cudaMemcpy2DAsync(outV + (size_t)1024 * 128, pitch,
                          cache_v + (size_t)1024 * 128, pitch, width, 64,
                          cudaMemcpyDeviceToDevice, s1);
    }
    splitT_kernel<<<dim3(128, 64), dim3(32, 8), 0, s1>>>(W_out, wo, 4096, 4096);
    cudaEventRecord(evPrep, s1);

    // main stream: W_qkv transpose runs concurrently with side stream
    splitT_kernel<<<dim3(384, 64), dim3(32, 8)>>>(W_qkv, bq, 4096, 12288);

    // ---- full QKV GEMM (do NOT split the well-packed GEMM) ----
    cudaStreamWaitEvent(0, evConv, 0);
    gemm_hmma<1><<<dim3(16, 96), 256, GEMM_SMEM>>>(ah, bq, b_qkv, 12288, 4096, 0,
                                                   nullptr, outK, outV);
    cudaEventRecord(evQKV, 0);

    // ---- staggered attention/out-proj overlap ----
    // stream0: attn(b0) -> outproj(rows b0)
    // stream1: waits attn(b0) done, then attn(b1) overlapping outproj(b0); outproj(b1)
    attn_hmma<<<dim3(16, 32), 128, ATT_SMEM>>>(0);
    cudaEventRecord(evA0, 0);

    cudaStreamWaitEvent(s1, evA0, 0);
    attn_hmma<<<dim3(16, 32), 128, ATT_SMEM, s1>>>(32);
    gemm_hmma<0><<<dim3(8, 32), 256, GEMM_SMEM, s1>>>(aout, wo, b_out, 4096, 4096, 1024,
                                                      y, nullptr, nullptr);
    cudaEventRecord(evDone1, s1);

    cudaStreamWaitEvent(0, evPrep, 0);
    gemm_hmma<0><<<dim3(8, 32), 256, GEMM_SMEM>>>(aout, wo, b_out, 4096, 4096, 0,
                                                  y, nullptr, nullptr);

    // join stream1
    cudaStreamWaitEvent(0, evDone1, 0);
}

// round 14
// speedup vs baseline: 1.0357x; 1.0357x over previous
#include <cuda_runtime.h>
#include <cuda_fp16.h>
#include <math.h>
#include <cstdint>

typedef unsigned long long u64;

// ==================== scratch ====================
__device__ __align__(128) __half g_ah[2048 * 4096];        // fp16(x) / A for QKV
__device__ __align__(128) __half g_aout_h[2048 * 4096];    // fp16 attn out / A for out-proj
__device__ __align__(128) __half g_qh[64 * 1024 * 128];
__device__ __align__(128) __half g_ql[64 * 1024 * 128];
__device__ __align__(128) __half g_kh[64 * 1024 * 128];
__device__ __align__(128) __half g_vh[64 * 1024 * 128];
__device__ __align__(128) __half g_bqkv[12288 * 4096];     // [N,K] fp16
__device__ __align__(128) __half g_wout[4096 * 4096];      // [N,K] fp16

// ==================== PTX helpers ====================
__device__ __forceinline__ uint32_t smem_u32(const void* p) {
    uint32_t a;
    asm("{ .reg .u64 t; cvta.to.shared.u64 t, %1; cvt.u32.u64 %0, t; }" : "=r"(a) : "l"(p));
    return a;
}
__device__ __forceinline__ uint32_t h2_as_u32(__half2 h) {
    union { __half2 h2; uint32_t u; } cvt;
    cvt.h2 = h;
    return cvt.u;
}
__device__ __forceinline__ __half2 u32_as_h2(uint32_t u) {
    union { uint32_t u; __half2 h2; } cvt;
    cvt.u = u;
    return cvt.h2;
}
__device__ __forceinline__ void cp16(uint32_t dst, const void* src) {
    asm volatile("cp.async.cg.shared.global [%0], [%1], 16;" :: "r"(dst), "l"(src));
}
__device__ __forceinline__ void cp_commit() { asm volatile("cp.async.commit_group;" ::: "memory"); }
template <int N> __device__ __forceinline__ void cp_wait() { asm volatile("cp.async.wait_group %0;" :: "n"(N) : "memory"); }

#define LDSM_X4(r0, r1, r2, r3, addr) \
    asm volatile("ldmatrix.sync.aligned.m8n8.x4.shared.b16 {%0,%1,%2,%3}, [%4];" \
        : "=r"(r0), "=r"(r1), "=r"(r2), "=r"(r3) : "r"(addr))
#define LDSM_X4_T(r0, r1, r2, r3, addr) \
    asm volatile("ldmatrix.sync.aligned.m8n8.x4.trans.shared.b16 {%0,%1,%2,%3}, [%4];" \
        : "=r"(r0), "=r"(r1), "=r"(r2), "=r"(r3) : "r"(addr))

#define MMA16816(d, a0, a1, a2, a3, b0, b1) \
    asm volatile("mma.sync.aligned.m16n8k16.row.col.f32.f16.f16.f32 " \
        "{%0,%1,%2,%3},{%4,%5,%6,%7},{%8,%9},{%0,%1,%2,%3};" \
        : "+f"((d)[0]), "+f"((d)[1]), "+f"((d)[2]), "+f"((d)[3]) \
        : "r"(a0), "r"(a1), "r"(a2), "r"(a3), "r"(b0), "r"(b1))

#define SMEM_SWZ(off)    ((off) ^ (((off) >> 3) & 0x70))   // 128B rows
#define SMEM_SWZ256(off) ((off) ^ (((off) >> 4) & 0x70))   // 256B rows

// ==================== prep kernels ====================
__global__ void __launch_bounds__(256) convert_h_kernel(const float* __restrict__ in,
                                                        __half* __restrict__ out) {
    const size_t i = (size_t)blockIdx.x * 256 + threadIdx.x;
    float4 v = ((const float4*)in)[i];
    __half2* op = (__half2*)out;
    op[2 * i]     = __floats2half2_rn(v.x, v.y);
    op[2 * i + 1] = __floats2half2_rn(v.z, v.w);
}

// W: [K,N] fp32 -> [N,K] fp16, half2 stores. block (32,8), tile 64k x 32n.
__global__ void __launch_bounds__(256) splitT_kernel(const float* __restrict__ in,
                                                     __half* __restrict__ outT, int K, int N) {
    __shared__ float t[64][33];
    const int n0 = blockIdx.x * 32, k0 = blockIdx.y * 64;
    const int tx = threadIdx.x, ty = threadIdx.y;
    #pragma unroll
    for (int i = ty; i < 64; i += 8)
        t[i][tx] = in[(size_t)(k0 + i) * N + n0 + tx];
    __syncthreads();
    #pragma unroll
    for (int i = ty; i < 32; i += 8) {
        const __half2 hv = __floats2half2_rn(t[tx * 2][i], t[tx * 2 + 1][i]);
        *(__half2*)(outT + (size_t)(n0 + i) * K + k0 + tx * 2) = hv;
    }
}

// ==================== HMMA GEMM (CTA 128x128, warp 64x32, 2 CTAs/SM) ====================
#define STG_BYTES 32768          // 16KB A + 16KB B
#define GEMM_SMEM (3 * STG_BYTES)

__device__ __forceinline__ void gemm_load_stage(
    const __half* __restrict__ A, const __half* __restrict__ Bt,
    int bm, int bn, int K, int kk, uint32_t stg, int tid)
{
    #pragma unroll
    for (int i = 0; i < 4; i++) {
        const int ch = tid + i * 256;
        const int r = ch >> 3, cc = ch & 7;
        cp16(stg + SMEM_SWZ((uint32_t)(r * 128 + cc * 16)),
             A + (size_t)(bm + r) * K + kk + cc * 8);
    }
    #pragma unroll
    for (int i = 0; i < 4; i++) {
        const int ch = tid + i * 256;
        const int r = ch >> 3, cc = ch & 7;
        cp16(stg + 16384 + SMEM_SWZ((uint32_t)(r * 128 + cc * 16)),
             Bt + (size_t)(bn + r) * K + kk + cc * 8);
    }
}

__device__ __forceinline__ void store_qkv_elem(int row, int col, float a, float b,
                                               float* __restrict__ outK, float* __restrict__ outV) {
    const int bb = row >> 10, s = row & 1023;
    const int seg = col >> 12, w = col & 4095;
    const int h = w >> 7, dd = w & 127;
    const int bh = bb * 32 + h;
    const __half ha = __float2half_rn(a), hb = __float2half_rn(b);
    const __half2 hh = __halves2half2(ha, hb);
    const size_t i16 = ((size_t)bh * 1024 + s) * 128 + dd;
    if (seg == 0) {
        const __half la = __float2half_rn(a - __half2float(ha));
        const __half lb = __float2half_rn(b - __half2float(hb));
        *(__half2*)(g_qh + i16) = hh;
        *(__half2*)(g_ql + i16) = __halves2half2(la, lb);
    } else if (seg == 1) {
        *(float2*)(outK + ((size_t)bh * 2048 + s) * 128 + dd) = float2{a, b};
        *(__half2*)(g_kh + i16) = hh;
    } else {
        *(float2*)(outV + ((size_t)bh * 2048 + s) * 128 + dd) = float2{a, b};
        *(__half2*)(g_vh + i16) = hh;
    }
}

template <int MODE>
__global__ void __launch_bounds__(256, 2) gemm_hmma(
    const __half* __restrict__ A, const __half* __restrict__ Bt,
    const float* __restrict__ bias, int N, int K,
    float* __restrict__ out0, float* __restrict__ outK, float* __restrict__ outV)
{
    extern __shared__ char smem[];
    const uint32_t sb = smem_u32(smem);
    const int tid = threadIdx.x;
    const int bm = blockIdx.x * 128;
    const int bn = blockIdx.y * 128;
    const int wid = tid >> 5, lane = tid & 31;
    const int wm = (wid & 1) * 64;
    const int wn = (wid >> 1) * 32;

    const int arow = wm + (lane & 15);
    const int achb = lane >> 4;
    const int brow = wn + (lane & 7) + ((lane & 16) >> 1);
    const int bchb = (lane >> 3) & 1;

    float acc[4][4][4];
    #pragma unroll
    for (int i = 0; i < 4; i++)
        #pragma unroll
        for (int j = 0; j < 4; j++)
            #pragma unroll
            for (int e = 0; e < 4; e++) acc[i][j][e] = 0.f;

    const int T = K >> 6;

    #pragma unroll
    for (int s = 0; s < 2; s++) {
        gemm_load_stage(A, Bt, bm, bn, K, s * 64, sb + s * STG_BYTES, tid);
        cp_commit();
    }

    for (int kt = 0; kt < T; kt++) {
        if (kt < T - 2) cp_wait<1>(); else cp_wait<0>();
        __syncthreads();

        if (kt + 2 < T) {
            gemm_load_stage(A, Bt, bm, bn, K, (kt + 2) * 64,
                            sb + ((kt + 2) % 3) * STG_BYTES, tid);
            cp_commit();
        }

        const uint32_t stg = sb + (kt % 3) * STG_BYTES;
        const uint32_t Ab = stg, Bb = stg + 16384;

        #pragma unroll
        for (int ks = 0; ks < 4; ks++) {
            uint32_t bfr[4][2];
            #pragma unroll
            for (int j2 = 0; j2 < 2; j2++) {
                const int rr = brow + j2 * 16;
                const int ch = (ks * 2 + bchb) ^ (rr & 7);
                uint32_t r0, r1, r2, r3;
                LDSM_X4(r0, r1, r2, r3, Bb + (uint32_t)(rr * 128 + ch * 16));
                bfr[j2 * 2 + 0][0] = r0; bfr[j2 * 2 + 0][1] = r1;
                bfr[j2 * 2 + 1][0] = r2; bfr[j2 * 2 + 1][1] = r3;
            }
            #pragma unroll
            for (int i = 0; i < 4; i++) {
                const int rr = arow + i * 16;
                const int ch = (ks * 2 + achb) ^ (rr & 7);
                uint32_t a0, a1, a2, a3;
                LDSM_X4(a0, a1, a2, a3, Ab + (uint32_t)(rr * 128 + ch * 16));
                #pragma unroll
                for (int j = 0; j < 4; j++)
                    MMA16816(acc[i][j], a0, a1, a2, a3, bfr[j][0], bfr[j][1]);
            }
        }
    }

    // epilogue
    const int lr = lane >> 2, lc2 = (lane & 3) * 2;
    #pragma unroll
    for (int i = 0; i < 4; i++) {
        #pragma unroll
        for (int j = 0; j < 4; j++) {
            const int c = bn + wn + j * 8 + lc2;
            const float bx = __ldg(bias + c);
            const float by = __ldg(bias + c + 1);
            const int r0 = bm + wm + i * 16 + lr;
            const float v0 = acc[i][j][0] + bx, v1 = acc[i][j][1] + by;
            const float v2 = acc[i][j][2] + bx, v3 = acc[i][j][3] + by;
            if (MODE == 0) {
                *(float2*)(out0 + (size_t)r0 * N + c) = float2{v0, v1};
                *(float2*)(out0 + (size_t)(r0 + 8) * N + c) = float2{v2, v3};
            } else {
                store_qkv_elem(r0, c, v0, v1, outK, outV);
                store_qkv_elem(r0 + 8, c, v2, v3, outK, outV);
            }
        }
    }
}

// ==================== HMMA flash attention (64 q-rows, 4 warps, 3 CTAs/SM) ====================
// QK = (qh+ql)*kh (K-lo pass dropped; error ~2.6e-4 added in quadrature).
// PV = ph*vh (denominator from rounded ph).
// Operand-phased single buffers: K(t+1) loads during softmax/PV; V(t+1) during next QK.
#define ATT_QH 0
#define ATT_QL 16384
#define ATT_KH 32768
#define ATT_VH 49152
#define ATT_SMEM 65536

__device__ __forceinline__ void attn_load_tile128(uint32_t dst, const __half* __restrict__ src,
                                                  int tid) {
    // 64 rows x 128 halves (256B rows, swizzled), 128 threads
    #pragma unroll
    for (int i = 0; i < 8; i++) {
        const int ch = tid + i * 128;
        const int r = ch >> 4, c = ch & 15;
        cp16(dst + SMEM_SWZ256((uint32_t)(r * 256 + c * 16)), src + (size_t)r * 128 + c * 8);
    }
}

__global__ void __launch_bounds__(128, 3) attn_hmma()
{
    extern __shared__ char smem[];
    const uint32_t sb = smem_u32(smem);
    const int qt = (int)gridDim.x - 1 - (int)blockIdx.x;   // longest-first schedule
    const int bh = blockIdx.y;
    const int b = bh >> 5, h = bh & 31;
    const int tid = threadIdx.x;
    const int wid = tid >> 5, lane = tid & 31;

    // Q tiles (group: Qh+Ql)
    const size_t qoff = ((size_t)bh * 1024 + qt * 64) * 128;
    attn_load_tile128(sb + ATT_QH, g_qh + qoff, tid);
    attn_load_tile128(sb + ATT_QL, g_ql + qoff, tid);
    cp_commit();

    const int nkt = qt + 1;
    const size_t kvbase = (size_t)bh * 1024 * 128;

    // prologue: K0, V0
    attn_load_tile128(sb + ATT_KH, g_kh + kvbase, tid);
    cp_commit();
    attn_load_tile128(sb + ATT_VH, g_vh + kvbase, tid);
    cp_commit();

    float o[16][4];
    #pragma unroll
    for (int nt = 0; nt < 16; nt++)
        #pragma unroll
        for (int e = 0; e < 4; e++) o[nt][e] = 0.f;
    float m1 = -INFINITY, m2 = -INFINITY, l1 = 0.f, l2 = 0.f;
    const float scale2 = 0.08838834764831845f * 1.4426950408889634f;  // scale*log2(e)

    const int row1 = qt * 64 + wid * 16 + (lane >> 2);
    const int row2 = row1 + 8;

    const int qar = wid * 16 + (lane & 15);
    const int qchb = lane >> 4;
    const int kbr = (lane & 7) + ((lane & 16) >> 1);
    const int kchb = (lane >> 3) & 1;
    const int vkv = lane & 15;
    const int vdc = lane >> 4;

    for (int kt = 0; kt < nkt; kt++) {
        // wait: Q + K_kt complete (V_kt may still be in flight)
        cp_wait<1>();
        __syncthreads();

        float s[8][4];
        #pragma unroll
        for (int nt = 0; nt < 8; nt++)
            #pragma unroll
            for (int e = 0; e < 4; e++) s[nt][e] = 0.f;

        // QK: (qh + ql) * kh
        #pragma unroll
        for (int ks = 0; ks < 8; ks++) {
            uint32_t bfr[8][2];
            #pragma unroll
            for (int j2 = 0; j2 < 4; j2++) {
                const int rr = kbr + j2 * 16;
                const int ch = (ks * 2 + kchb) ^ (lane & 7);
                uint32_t r0, r1, r2, r3;
                LDSM_X4(r0, r1, r2, r3, sb + ATT_KH + (uint32_t)(rr * 256 + ch * 16));
                bfr[j2 * 2][0] = r0; bfr[j2 * 2][1] = r1;
                bfr[j2 * 2 + 1][0] = r2; bfr[j2 * 2 + 1][1] = r3;
            }
            const int ch = (ks * 2 + qchb) ^ (qar & 7);
            uint32_t a0, a1, a2, a3;
            LDSM_X4(a0, a1, a2, a3, sb + ATT_QH + (uint32_t)(qar * 256 + ch * 16));
            #pragma unroll
            for (int j = 0; j < 8; j++) MMA16816(s[j], a0, a1, a2, a3, bfr[j][0], bfr[j][1]);
            LDSM_X4(a0, a1, a2, a3, sb + ATT_QL + (uint32_t)(qar * 256 + ch * 16));
            #pragma unroll
            for (int j = 0; j < 8; j++) MMA16816(s[j], a0, a1, a2, a3, bfr[j][0], bfr[j][1]);
        }

        // K buffer free -> start K(t+1) load
        __syncthreads();
        if (kt + 1 < nkt) {
            attn_load_tile128(sb + ATT_KH, g_kh + kvbase + (size_t)(kt + 1) * 64 * 128, tid);
            cp_commit();
        }

        // scale (base-2) + mask (diagonal tile only) + online softmax
        const bool need_mask = (kt == qt);
        float mx1 = -INFINITY, mx2 = -INFINITY;
        #pragma unroll
        for (int nt = 0; nt < 8; nt++) {
            const int cg = kt * 64 + nt * 8 + (lane & 3) * 2;
            #pragma unroll
            for (int e = 0; e < 2; e++) {
                float v = s[nt][e] * scale2;
                if (need_mask && (cg + e > row1)) v = -INFINITY;
                s[nt][e] = v; mx1 = fmaxf(mx1, v);
            }
            #pragma unroll
            for (int e = 2; e < 4; e++) {
                float v = s[nt][e] * scale2;
                if (need_mask && (cg + e - 2 > row2)) v = -INFINITY;
                s[nt][e] = v; mx2 = fmaxf(mx2, v);
            }
        }
        mx1 = fmaxf(mx1, __shfl_xor_sync(0xffffffffu, mx1, 1));
        mx1 = fmaxf(mx1, __shfl_xor_sync(0xffffffffu, mx1, 2));
        mx2 = fmaxf(mx2, __shfl_xor_sync(0xffffffffu, mx2, 1));
        mx2 = fmaxf(mx2, __shfl_xor_sync(0xffffffffu, mx2, 2));
        const float mn1 = fmaxf(m1, mx1), mn2 = fmaxf(m2, mx2);
        const float c1 = exp2f(m1 - mn1), c2 = exp2f(m2 - mn2);
        m1 = mn1; m2 = mn2;

        uint32_t ph2[8][2];
        float ts1 = 0.f, ts2 = 0.f;
        #pragma unroll
        for (int nt = 0; nt < 8; nt++) {
            const uint32_t u1 = h2_as_u32(__floats2half2_rn(s[nt][0] - mn1, s[nt][1] - mn1));
            const uint32_t u2 = h2_as_u32(__floats2half2_rn(s[nt][2] - mn2, s[nt][3] - mn2));
            uint32_t r1u, r2u;
            asm("ex2.approx.f16x2 %0, %1;" : "=r"(r1u) : "r"(u1));
            asm("ex2.approx.f16x2 %0, %1;" : "=r"(r2u) : "r"(u2));
            ph2[nt][0] = r1u; ph2[nt][1] = r2u;
            const float2 f1 = __half22float2(u32_as_h2(r1u));
            const float2 f2 = __half22float2(u32_as_h2(r2u));
            ts1 += f1.x + f1.y;
            ts2 += f2.x + f2.y;
        }
        l1 = l1 * c1 + ts1; l2 = l2 * c2 + ts2;
        #pragma unroll
        for (int nt = 0; nt < 16; nt++) {
            o[nt][0] *= c1; o[nt][1] *= c1; o[nt][2] *= c2; o[nt][3] *= c2;
        }

        // wait: V_kt complete (K(t+1) may be pending)
        if (kt + 1 < nkt) cp_wait<1>(); else cp_wait<0>();
        __syncthreads();

        // PV: ph * vh
        #pragma unroll
        for (int ks = 0; ks < 4; ks++) {
            const uint32_t ah0 = ph2[2 * ks][0], ah1 = ph2[2 * ks][1];
            const uint32_t ah2 = ph2[2 * ks + 1][0], ah3 = ph2[2 * ks + 1][1];
            #pragma unroll
            for (int d2 = 0; d2 < 8; d2++) {
                const int kvr = ks * 16 + vkv;
                const int ch = (d2 * 2 + vdc) ^ (vkv & 7);
                const uint32_t va = (uint32_t)(kvr * 256 + ch * 16);
                uint32_t v0, v1, v2, v3;
                LDSM_X4_T(v0, v1, v2, v3, sb + ATT_VH + va);
                MMA16816(o[2 * d2],     ah0, ah1, ah2, ah3, v0, v1);
                MMA16816(o[2 * d2 + 1], ah0, ah1, ah2, ah3, v2, v3);
            }
        }

        // V buffer free -> start V(t+1) load
        __syncthreads();
        if (kt + 1 < nkt) {
            attn_load_tile128(sb + ATT_VH, g_vh + kvbase + (size_t)(kt + 1) * 64 * 128, tid);
            cp_commit();
        }
    }

    l1 += __shfl_xor_sync(0xffffffffu, l1, 1);
    l1 += __shfl_xor_sync(0xffffffffu, l1, 2);
    l2 += __shfl_xor_sync(0xffffffffu, l2, 1);
    l2 += __shfl_xor_sync(0xffffffffu, l2, 2);
    const float i1 = 1.f / l1, i2 = 1.f / l2;

    __half* outp = g_aout_h;
    #pragma unroll
    for (int nt = 0; nt < 16; nt++) {
        const int col = h * 128 + nt * 8 + (lane & 3) * 2;
        *(__half2*)(outp + (size_t)(b * 1024 + row1) * 4096 + col) =
            __floats2half2_rn(o[nt][0] * i1, o[nt][1] * i1);
        *(__half2*)(outp + (size_t)(b * 1024 + row2) * 4096 + col) =
            __floats2half2_rn(o[nt][2] * i2, o[nt][3] * i2);
    }
}

// ==================== launch ====================
extern "C" void kernel_launch(void* const* d_in, const int* in_sizes, int n_in,
                              void* d_out, int out_size)
{
    const float* x       = (const float*)d_in[0];
    const float* W_qkv   = (const float*)d_in[2];
    const float* b_qkv   = (const float*)d_in[3];
    const float* W_out   = (const float*)d_in[4];
    const float* b_out   = (const float*)d_in[5];
    const float* cache_k = (const float*)d_in[6];
    const float* cache_v = (const float*)d_in[7];

    float* out  = (float*)d_out;
    float* y    = out;
    float* outK = out + 8388608;
    float* outV = out + 25165824;

    __half *ah, *aout, *bq, *wo;
    cudaGetSymbolAddress((void**)&ah, g_ah);
    cudaGetSymbolAddress((void**)&aout, g_aout_h);
    cudaGetSymbolAddress((void**)&bq, g_bqkv);
    cudaGetSymbolAddress((void**)&wo, g_wout);

    // one-time side-stream + fork/join events (no device memory involved)
    static cudaStream_t s1 = nullptr;
    static cudaEvent_t evFork = nullptr, evConv = nullptr, evPrep = nullptr;
    if (s1 == nullptr) {
        cudaStreamCreateWithFlags(&s1, cudaStreamNonBlocking);
        cudaEventCreateWithFlags(&evFork, cudaEventDisableTiming);
        cudaEventCreateWithFlags(&evConv, cudaEventDisableTiming);
        cudaEventCreateWithFlags(&evPrep, cudaEventDisableTiming);
    }

    cudaFuncSetAttribute(gemm_hmma<0>, cudaFuncAttributeMaxDynamicSharedMemorySize, GEMM_SMEM);
    cudaFuncSetAttribute(gemm_hmma<1>, cudaFuncAttributeMaxDynamicSharedMemorySize, GEMM_SMEM);
    cudaFuncSetAttribute(attn_hmma, cudaFuncAttributeMaxDynamicSharedMemorySize, ATT_SMEM);

    // ---- fork side stream ----
    cudaEventRecord(evFork, 0);
    cudaStreamWaitEvent(s1, evFork, 0);

    // side stream: x->fp16, cache tail copies, W_out transpose
    convert_h_kernel<<<8192, 256, 0, s1>>>(x, ah);
    cudaEventRecord(evConv, s1);
    {
        const size_t pitch = (size_t)2048 * 128 * sizeof(float);
        const size_t width = (size_t)1024 * 128 * sizeof(float);
        cudaMemcpy2DAsync(outK + (size_t)1024 * 128, pitch,
                          cache_k + (size_t)1024 * 128, pitch, width, 64,
                          cudaMemcpyDeviceToDevice, s1);
        cudaMemcpy2DAsync(outV + (size_t)1024 * 128, pitch,
                          cache_v + (size_t)1024 * 128, pitch, width, 64,
                          cudaMemcpyDeviceToDevice, s1);
    }
    splitT_kernel<<<dim3(128, 64), dim3(32, 8), 0, s1>>>(W_out, wo, 4096, 4096);
    cudaEventRecord(evPrep, s1);

    // main stream: W_qkv transpose runs concurrently with side stream
    splitT_kernel<<<dim3(384, 64), dim3(32, 8)>>>(W_qkv, bq, 4096, 12288);

    // QKV GEMM needs g_ah (side stream)
    cudaStreamWaitEvent(0, evConv, 0);
    gemm_hmma<1><<<dim3(16, 96), 256, GEMM_SMEM>>>(ah, bq, b_qkv, 12288, 4096,
                                                   nullptr, outK, outV);

    attn_hmma<<<dim3(16, 64), 128, ATT_SMEM>>>();

    // out-proj needs g_wout (side stream) — join before launch
    cudaStreamWaitEvent(0, evPrep, 0);
    gemm_hmma<0><<<dim3(16, 32), 256, GEMM_SMEM>>>(aout, wo, b_out, 4096, 4096,
                                                   y, nullptr, nullptr);
}

// round 15
// speedup vs baseline: 1.0651x; 1.0284x over previous
#include <cuda_runtime.h>
#include <cuda_fp16.h>
#include <math.h>
#include <cstdint>

typedef unsigned long long u64;

// ==================== scratch ====================
__device__ __align__(128) __half g_ah[2048 * 4096];        // fp16(x) / A for QKV
__device__ __align__(128) __half g_aout_h[2048 * 4096];    // fp16 attn out / A for out-proj
__device__ __align__(128) __half g_qh[64 * 1024 * 128];
__device__ __align__(128) __half g_kh[64 * 1024 * 128];
__device__ __align__(128) __half g_vh[64 * 1024 * 128];
__device__ __align__(128) __half g_bqkv[12288 * 4096];     // [N,K] fp16
__device__ __align__(128) __half g_wout[4096 * 4096];      // [N,K] fp16

// ==================== PTX helpers ====================
__device__ __forceinline__ uint32_t smem_u32(const void* p) {
    uint32_t a;
    asm("{ .reg .u64 t; cvta.to.shared.u64 t, %1; cvt.u32.u64 %0, t; }" : "=r"(a) : "l"(p));
    return a;
}
__device__ __forceinline__ uint32_t h2_as_u32(__half2 h) {
    union { __half2 h2; uint32_t u; } cvt;
    cvt.h2 = h;
    return cvt.u;
}
__device__ __forceinline__ __half2 u32_as_h2(uint32_t u) {
    union { uint32_t u; __half2 h2; } cvt;
    cvt.u = u;
    return cvt.h2;
}
__device__ __forceinline__ void cp16(uint32_t dst, const void* src) {
    asm volatile("cp.async.cg.shared.global [%0], [%1], 16;" :: "r"(dst), "l"(src));
}
__device__ __forceinline__ void cp_commit() { asm volatile("cp.async.commit_group;" ::: "memory"); }
template <int N> __device__ __forceinline__ void cp_wait() { asm volatile("cp.async.wait_group %0;" :: "n"(N) : "memory"); }

#define LDSM_X4(r0, r1, r2, r3, addr) \
    asm volatile("ldmatrix.sync.aligned.m8n8.x4.shared.b16 {%0,%1,%2,%3}, [%4];" \
        : "=r"(r0), "=r"(r1), "=r"(r2), "=r"(r3) : "r"(addr))
#define LDSM_X4_T(r0, r1, r2, r3, addr) \
    asm volatile("ldmatrix.sync.aligned.m8n8.x4.trans.shared.b16 {%0,%1,%2,%3}, [%4];" \
        : "=r"(r0), "=r"(r1), "=r"(r2), "=r"(r3) : "r"(addr))

#define MMA16816(d, a0, a1, a2, a3, b0, b1) \
    asm volatile("mma.sync.aligned.m16n8k16.row.col.f32.f16.f16.f32 " \
        "{%0,%1,%2,%3},{%4,%5,%6,%7},{%8,%9},{%0,%1,%2,%3};" \
        : "+f"((d)[0]), "+f"((d)[1]), "+f"((d)[2]), "+f"((d)[3]) \
        : "r"(a0), "r"(a1), "r"(a2), "r"(a3), "r"(b0), "r"(b1))

#define SMEM_SWZ(off)    ((off) ^ (((off) >> 3) & 0x70))   // 128B rows
#define SMEM_SWZ256(off) ((off) ^ (((off) >> 4) & 0x70))   // 256B rows

// ==================== prep kernels ====================
__global__ void __launch_bounds__(256) convert_h_kernel(const float* __restrict__ in,
                                                        __half* __restrict__ out) {
    const size_t i = (size_t)blockIdx.x * 256 + threadIdx.x;
    float4 v = ((const float4*)in)[i];
    __half2* op = (__half2*)out;
    op[2 * i]     = __floats2half2_rn(v.x, v.y);
    op[2 * i + 1] = __floats2half2_rn(v.z, v.w);
}

// W: [K,N] fp32 -> [N,K] fp16, half2 stores. block (32,8), tile 64k x 32n.
__global__ void __launch_bounds__(256) splitT_kernel(const float* __restrict__ in,
                                                     __half* __restrict__ outT, int K, int N) {
    __shared__ float t[64][33];
    const int n0 = blockIdx.x * 32, k0 = blockIdx.y * 64;
    const int tx = threadIdx.x, ty = threadIdx.y;
    #pragma unroll
    for (int i = ty; i < 64; i += 8)
        t[i][tx] = in[(size_t)(k0 + i) * N + n0 + tx];
    __syncthreads();
    #pragma unroll
    for (int i = ty; i < 32; i += 8) {
        const __half2 hv = __floats2half2_rn(t[tx * 2][i], t[tx * 2 + 1][i]);
        *(__half2*)(outT + (size_t)(n0 + i) * K + k0 + tx * 2) = hv;
    }
}

// ==================== HMMA GEMM (CTA 128x128, warp 64x32, 2 CTAs/SM) ====================
#define STG_BYTES 32768          // 16KB A + 16KB B
#define GEMM_SMEM (3 * STG_BYTES)

__device__ __forceinline__ void gemm_load_stage(
    const __half* __restrict__ A, const __half* __restrict__ Bt,
    int bm, int bn, int K, int kk, uint32_t stg, int tid)
{
    #pragma unroll
    for (int i = 0; i < 4; i++) {
        const int ch = tid + i * 256;
        const int r = ch >> 3, cc = ch & 7;
        cp16(stg + SMEM_SWZ((uint32_t)(r * 128 + cc * 16)),
             A + (size_t)(bm + r) * K + kk + cc * 8);
    }
    #pragma unroll
    for (int i = 0; i < 4; i++) {
        const int ch = tid + i * 256;
        const int r = ch >> 3, cc = ch & 7;
        cp16(stg + 16384 + SMEM_SWZ((uint32_t)(r * 128 + cc * 16)),
             Bt + (size_t)(bn + r) * K + kk + cc * 8);
    }
}

__device__ __forceinline__ void store_qkv_elem(int row, int col, float a, float b,
                                               float* __restrict__ outK, float* __restrict__ outV) {
    const int bb = row >> 10, s = row & 1023;
    const int seg = col >> 12, w = col & 4095;
    const int h = w >> 7, dd = w & 127;
    const int bh = bb * 32 + h;
    const __half2 hh = __floats2half2_rn(a, b);
    const size_t i16 = ((size_t)bh * 1024 + s) * 128 + dd;
    if (seg == 0) {
        *(__half2*)(g_qh + i16) = hh;
    } else if (seg == 1) {
        *(float2*)(outK + ((size_t)bh * 2048 + s) * 128 + dd) = float2{a, b};
        *(__half2*)(g_kh + i16) = hh;
    } else {
        *(float2*)(outV + ((size_t)bh * 2048 + s) * 128 + dd) = float2{a, b};
        *(__half2*)(g_vh + i16) = hh;
    }
}

template <int MODE>
__global__ void __launch_bounds__(256, 2) gemm_hmma(
    const __half* __restrict__ A, const __half* __restrict__ Bt,
    const float* __restrict__ bias, int N, int K,
    float* __restrict__ out0, float* __restrict__ outK, float* __restrict__ outV)
{
    extern __shared__ char smem[];
    const uint32_t sb = smem_u32(smem);
    const int tid = threadIdx.x;
    const int bm = blockIdx.x * 128;
    const int bn = blockIdx.y * 128;
    const int wid = tid >> 5, lane = tid & 31;
    const int wm = (wid & 1) * 64;
    const int wn = (wid >> 1) * 32;

    const int arow = wm + (lane & 15);
    const int achb = lane >> 4;
    const int brow = wn + (lane & 7) + ((lane & 16) >> 1);
    const int bchb = (lane >> 3) & 1;

    float acc[4][4][4];
    #pragma unroll
    for (int i = 0; i < 4; i++)
        #pragma unroll
        for (int j = 0; j < 4; j++)
            #pragma unroll
            for (int e = 0; e < 4; e++) acc[i][j][e] = 0.f;

    const int T = K >> 6;

    #pragma unroll
    for (int s = 0; s < 2; s++) {
        gemm_load_stage(A, Bt, bm, bn, K, s * 64, sb + s * STG_BYTES, tid);
        cp_commit();
    }

    for (int kt = 0; kt < T; kt++) {
        if (kt < T - 2) cp_wait<1>(); else cp_wait<0>();
        __syncthreads();

        if (kt + 2 < T) {
            gemm_load_stage(A, Bt, bm, bn, K, (kt + 2) * 64,
                            sb + ((kt + 2) % 3) * STG_BYTES, tid);
            cp_commit();
        }

        const uint32_t stg = sb + (kt % 3) * STG_BYTES;
        const uint32_t Ab = stg, Bb = stg + 16384;

        #pragma unroll
        for (int ks = 0; ks < 4; ks++) {
            uint32_t bfr[4][2];
            #pragma unroll
            for (int j2 = 0; j2 < 2; j2++) {
                const int rr = brow + j2 * 16;
                const int ch = (ks * 2 + bchb) ^ (rr & 7);
                uint32_t r0, r1, r2, r3;
                LDSM_X4(r0, r1, r2, r3, Bb + (uint32_t)(rr * 128 + ch * 16));
                bfr[j2 * 2 + 0][0] = r0; bfr[j2 * 2 + 0][1] = r1;
                bfr[j2 * 2 + 1][0] = r2; bfr[j2 * 2 + 1][1] = r3;
            }
            #pragma unroll
            for (int i = 0; i < 4; i++) {
                const int rr = arow + i * 16;
                const int ch = (ks * 2 + achb) ^ (rr & 7);
                uint32_t a0, a1, a2, a3;
                LDSM_X4(a0, a1, a2, a3, Ab + (uint32_t)(rr * 128 + ch * 16));
                #pragma unroll
                for (int j = 0; j < 4; j++)
                    MMA16816(acc[i][j], a0, a1, a2, a3, bfr[j][0], bfr[j][1]);
            }
        }
    }

    // epilogue
    const int lr = lane >> 2, lc2 = (lane & 3) * 2;
    #pragma unroll
    for (int i = 0; i < 4; i++) {
        #pragma unroll
        for (int j = 0; j < 4; j++) {
            const int c = bn + wn + j * 8 + lc2;
            const float bx = __ldg(bias + c);
            const float by = __ldg(bias + c + 1);
            const int r0 = bm + wm + i * 16 + lr;
            const float v0 = acc[i][j][0] + bx, v1 = acc[i][j][1] + by;
            const float v2 = acc[i][j][2] + bx, v3 = acc[i][j][3] + by;
            if (MODE == 0) {
                *(float2*)(out0 + (size_t)r0 * N + c) = float2{v0, v1};
                *(float2*)(out0 + (size_t)(r0 + 8) * N + c) = float2{v2, v3};
            } else {
                store_qkv_elem(r0, c, v0, v1, outK, outV);
                store_qkv_elem(r0 + 8, c, v2, v3, outK, outV);
            }
        }
    }
}

// ==================== HMMA flash attention (64 q-rows, 4 warps, 3 CTAs/SM) ====================
// QK = qh*kh (single pass; ql and kl contributions dropped — calibrated error model:
// each adds ~2.86e-4 independently; total predicted ~8.65e-4 < 1e-3).
// PV = ph*vh (denominator from rounded ph).
// Operand-phased single buffers: K(t+1) loads during softmax/PV; V(t+1) during next QK.
#define ATT_QH 0
#define ATT_KH 16384
#define ATT_VH 32768
#define ATT_SMEM 49152

__device__ __forceinline__ void attn_load_tile128(uint32_t dst, const __half* __restrict__ src,
                                                  int tid) {
    // 64 rows x 128 halves (256B rows, swizzled), 128 threads
    #pragma unroll
    for (int i = 0; i < 8; i++) {
        const int ch = tid + i * 128;
        const int r = ch >> 4, c = ch & 15;
        cp16(dst + SMEM_SWZ256((uint32_t)(r * 256 + c * 16)), src + (size_t)r * 128 + c * 8);
    }
}

__global__ void __launch_bounds__(128, 3) attn_hmma()
{
    extern __shared__ char smem[];
    const uint32_t sb = smem_u32(smem);
    const int qt = (int)gridDim.x - 1 - (int)blockIdx.x;   // longest-first schedule
    const int bh = blockIdx.y;
    const int b = bh >> 5, h = bh & 31;
    const int tid = threadIdx.x;
    const int wid = tid >> 5, lane = tid & 31;

    // Q tile
    const size_t qoff = ((size_t)bh * 1024 + qt * 64) * 128;
    attn_load_tile128(sb + ATT_QH, g_qh + qoff, tid);
    cp_commit();

    const int nkt = qt + 1;
    const size_t kvbase = (size_t)bh * 1024 * 128;

    // prologue: K0, V0
    attn_load_tile128(sb + ATT_KH, g_kh + kvbase, tid);
    cp_commit();
    attn_load_tile128(sb + ATT_VH, g_vh + kvbase, tid);
    cp_commit();

    float o[16][4];
    #pragma unroll
    for (int nt = 0; nt < 16; nt++)
        #pragma unroll
        for (int e = 0; e < 4; e++) o[nt][e] = 0.f;
    float m1 = -INFINITY, m2 = -INFINITY, l1 = 0.f, l2 = 0.f;
    const float scale2 = 0.08838834764831845f * 1.4426950408889634f;  // scale*log2(e)

    const int row1 = qt * 64 + wid * 16 + (lane >> 2);
    const int row2 = row1 + 8;

    const int qar = wid * 16 + (lane & 15);
    const int qchb = lane >> 4;
    const int kbr = (lane & 7) + ((lane & 16) >> 1);
    const int kchb = (lane >> 3) & 1;
    const int vkv = lane & 15;
    const int vdc = lane >> 4;

    for (int kt = 0; kt < nkt; kt++) {
        // wait: Q + K_kt complete (V_kt may still be in flight)
        cp_wait<1>();
        __syncthreads();

        float s[8][4];
        #pragma unroll
        for (int nt = 0; nt < 8; nt++)
            #pragma unroll
            for (int e = 0; e < 4; e++) s[nt][e] = 0.f;

        // QK: qh * kh (single pass)
        #pragma unroll
        for (int ks = 0; ks < 8; ks++) {
            uint32_t bfr[8][2];
            #pragma unroll
            for (int j2 = 0; j2 < 4; j2++) {
                const int rr = kbr + j2 * 16;
                const int ch = (ks * 2 + kchb) ^ (lane & 7);
                uint32_t r0, r1, r2, r3;
                LDSM_X4(r0, r1, r2, r3, sb + ATT_KH + (uint32_t)(rr * 256 + ch * 16));
                bfr[j2 * 2][0] = r0; bfr[j2 * 2][1] = r1;
                bfr[j2 * 2 + 1][0] = r2; bfr[j2 * 2 + 1][1] = r3;
            }
            const int ch = (ks * 2 + qchb) ^ (qar & 7);
            uint32_t a0, a1, a2, a3;
            LDSM_X4(a0, a1, a2, a3, sb + ATT_QH + (uint32_t)(qar * 256 + ch * 16));
            #pragma unroll
            for (int j = 0; j < 8; j++) MMA16816(s[j], a0, a1, a2, a3, bfr[j][0], bfr[j][1]);
        }

        // K buffer free -> start K(t+1) load
        __syncthreads();
        if (kt + 1 < nkt) {
            attn_load_tile128(sb + ATT_KH, g_kh + kvbase + (size_t)(kt + 1) * 64 * 128, tid);
            cp_commit();
        }

        // scale (base-2) + mask (diagonal tile only) + online softmax
        const bool need_mask = (kt == qt);
        float mx1 = -INFINITY, mx2 = -INFINITY;
        #pragma unroll
        for (int nt = 0; nt < 8; nt++) {
            const int cg = kt * 64 + nt * 8 + (lane & 3) * 2;
            #pragma unroll
            for (int e = 0; e < 2; e++) {
                float v = s[nt][e] * scale2;
                if (need_mask && (cg + e > row1)) v = -INFINITY;
                s[nt][e] = v; mx1 = fmaxf(mx1, v);
            }
            #pragma unroll
            for (int e = 2; e < 4; e++) {
                float v = s[nt][e] * scale2;
                if (need_mask && (cg + e - 2 > row2)) v = -INFINITY;
                s[nt][e] = v; mx2 = fmaxf(mx2, v);
            }
        }
        mx1 = fmaxf(mx1, __shfl_xor_sync(0xffffffffu, mx1, 1));
        mx1 = fmaxf(mx1, __shfl_xor_sync(0xffffffffu, mx1, 2));
        mx2 = fmaxf(mx2, __shfl_xor_sync(0xffffffffu, mx2, 1));
        mx2 = fmaxf(mx2, __shfl_xor_sync(0xffffffffu, mx2, 2));
        const float mn1 = fmaxf(m1, mx1), mn2 = fmaxf(m2, mx2);
        const float c1 = exp2f(m1 - mn1), c2 = exp2f(m2 - mn2);
        m1 = mn1; m2 = mn2;

        uint32_t ph2[8][2];
        float ts1 = 0.f, ts2 = 0.f;
        #pragma unroll
        for (int nt = 0; nt < 8; nt++) {
            const uint32_t u1 = h2_as_u32(__floats2half2_rn(s[nt][0] - mn1, s[nt][1] - mn1));
            const uint32_t u2 = h2_as_u32(__floats2half2_rn(s[nt][2] - mn2, s[nt][3] - mn2));
            uint32_t r1u, r2u;
            asm("ex2.approx.f16x2 %0, %1;" : "=r"(r1u) : "r"(u1));
            asm("ex2.approx.f16x2 %0, %1;" : "=r"(r2u) : "r"(u2));
            ph2[nt][0] = r1u; ph2[nt][1] = r2u;
            const float2 f1 = __half22float2(u32_as_h2(r1u));
            const float2 f2 = __half22float2(u32_as_h2(r2u));
            ts1 += f1.x + f1.y;
            ts2 += f2.x + f2.y;
        }
        l1 = l1 * c1 + ts1; l2 = l2 * c2 + ts2;
        #pragma unroll
        for (int nt = 0; nt < 16; nt++) {
            o[nt][0] *= c1; o[nt][1] *= c1; o[nt][2] *= c2; o[nt][3] *= c2;
        }

        // wait: V_kt complete (K(t+1) may be pending)
        if (kt + 1 < nkt) cp_wait<1>(); else cp_wait<0>();
        __syncthreads();

        // PV: ph * vh
        #pragma unroll
        for (int ks = 0; ks < 4; ks++) {
            const uint32_t ah0 = ph2[2 * ks][0], ah1 = ph2[2 * ks][1];
            const uint32_t ah2 = ph2[2 * ks + 1][0], ah3 = ph2[2 * ks + 1][1];
            #pragma unroll
            for (int d2 = 0; d2 < 8; d2++) {
                const int kvr = ks * 16 + vkv;
                const int ch = (d2 * 2 + vdc) ^ (vkv & 7);
                const uint32_t va = (uint32_t)(kvr * 256 + ch * 16);
                uint32_t v0, v1, v2, v3;
                LDSM_X4_T(v0, v1, v2, v3, sb + ATT_VH + va);
                MMA16816(o[2 * d2],     ah0, ah1, ah2, ah3, v0, v1);
                MMA16816(o[2 * d2 + 1], ah0, ah1, ah2, ah3, v2, v3);
            }
        }

        // V buffer free -> start V(t+1) load
        __syncthreads();
        if (kt + 1 < nkt) {
            attn_load_tile128(sb + ATT_VH, g_vh + kvbase + (size_t)(kt + 1) * 64 * 128, tid);
            cp_commit();
        }
    }

    l1 += __shfl_xor_sync(0xffffffffu, l1, 1);
    l1 += __shfl_xor_sync(0xffffffffu, l1, 2);
    l2 += __shfl_xor_sync(0xffffffffu, l2, 1);
    l2 += __shfl_xor_sync(0xffffffffu, l2, 2);
    const float i1 = 1.f / l1, i2 = 1.f / l2;

    __half* outp = g_aout_h;
    #pragma unroll
    for (int nt = 0; nt < 16; nt++) {
        const int col = h * 128 + nt * 8 + (lane & 3) * 2;
        *(__half2*)(outp + (size_t)(b * 1024 + row1) * 4096 + col) =
            __floats2half2_rn(o[nt][0] * i1, o[nt][1] * i1);
        *(__half2*)(outp + (size_t)(b * 1024 + row2) * 4096 + col) =
            __floats2half2_rn(o[nt][2] * i2, o[nt][3] * i2);
    }
}

// ==================== launch ====================
extern "C" void kernel_launch(void* const* d_in, const int* in_sizes, int n_in,
                              void* d_out, int out_size)
{
    const float* x       = (const float*)d_in[0];
    const float* W_qkv   = (const float*)d_in[2];
    const float* b_qkv   = (const float*)d_in[3];
    const float* W_out   = (const float*)d_in[4];
    const float* b_out   = (const float*)d_in[5];
    const float* cache_k = (const float*)d_in[6];
    const float* cache_v = (const float*)d_in[7];

    float* out  = (float*)d_out;
    float* y    = out;
    float* outK = out + 8388608;
    float* outV = out + 25165824;

    __half *ah, *aout, *bq, *wo;
    cudaGetSymbolAddress((void**)&ah, g_ah);
    cudaGetSymbolAddress((void**)&aout, g_aout_h);
    cudaGetSymbolAddress((void**)&bq, g_bqkv);
    cudaGetSymbolAddress((void**)&wo, g_wout);

    // one-time side-stream + fork/join events (no device memory involved)
    static cudaStream_t s1 = nullptr;
    static cudaEvent_t evFork = nullptr, evConv = nullptr, evPrep = nullptr;
    if (s1 == nullptr) {
        cudaStreamCreateWithFlags(&s1, cudaStreamNonBlocking);
        cudaEventCreateWithFlags(&evFork, cudaEventDisableTiming);
        cudaEventCreateWithFlags(&evConv, cudaEventDisableTiming);
        cudaEventCreateWithFlags(&evPrep, cudaEventDisableTiming);
    }

    cudaFuncSetAttribute(gemm_hmma<0>, cudaFuncAttributeMaxDynamicSharedMemorySize, GEMM_SMEM);
    cudaFuncSetAttribute(gemm_hmma<1>, cudaFuncAttributeMaxDynamicSharedMemorySize, GEMM_SMEM);
    cudaFuncSetAttribute(attn_hmma, cudaFuncAttributeMaxDynamicSharedMemorySize, ATT_SMEM);

    // ---- fork side stream ----
    cudaEventRecord(evFork, 0);
    cudaStreamWaitEvent(s1, evFork, 0);

    // side stream: x->fp16, cache tail copies, W_out transpose
    convert_h_kernel<<<8192, 256, 0, s1>>>(x, ah);
    cudaEventRecord(evConv, s1);
    {
        const size_t pitch = (size_t)2048 * 128 * sizeof(float);
        const size_t width = (size_t)1024 * 128 * sizeof(float);
        cudaMemcpy2DAsync(outK + (size_t)1024 * 128, pitch,
                          cache_k + (size_t)1024 * 128, pitch, width, 64,
                          cudaMemcpyDeviceToDevice, s1);
        cudaMemcpy2DAsync(outV + (size_t)1024 * 128, pitch,
                          cache_v + (size_t)1024 * 128, pitch, width, 64,
                          cudaMemcpyDeviceToDevice, s1);
    }
    splitT_kernel<<<dim3(128, 64), dim3(32, 8), 0, s1>>>(W_out, wo, 4096, 4096);
    cudaEventRecord(evPrep, s1);

    // main stream: W_qkv transpose runs concurrently with side stream
    splitT_kernel<<<dim3(384, 64), dim3(32, 8)>>>(W_qkv, bq, 4096, 12288);

    // QKV GEMM needs g_ah (side stream)
    cudaStreamWaitEvent(0, evConv, 0);
    gemm_hmma<1><<<dim3(16, 96), 256, GEMM_SMEM>>>(ah, bq, b_qkv, 12288, 4096,
                                                   nullptr, outK, outV);

    attn_hmma<<<dim3(16, 64), 128, ATT_SMEM>>>();

    // out-proj needs g_wout (side stream) — join before launch
    cudaStreamWaitEvent(0, evPrep, 0);
    gemm_hmma<0><<<dim3(16, 32), 256, GEMM_SMEM>>>(aout, wo, b_out, 4096, 4096,
                                                   y, nullptr, nullptr);
}

// round 16
// speedup vs baseline: 1.1123x; 1.0442x over previous
#include <cuda_runtime.h>
#include <cuda_fp16.h>
#include <math.h>
#include <cstdint>

typedef unsigned long long u64;

// ==================== scratch ====================
__device__ __align__(128) __half g_ah[2048 * 4096];        // fp16(x) / A for QKV
__device__ __align__(128) __half g_aout_h[2048 * 4096];    // fp16 attn out / A for out-proj
__device__ __align__(128) __half g_qh[64 * 1024 * 128];
__device__ __align__(128) __half g_kh[64 * 1024 * 128];
__device__ __align__(128) __half g_vh[64 * 1024 * 128];
__device__ __align__(128) __half g_bqkv[12288 * 4096];     // [N,K] fp16
__device__ __align__(128) __half g_wout[4096 * 4096];      // [N,K] fp16

// ==================== PTX helpers ====================
__device__ __forceinline__ uint32_t smem_u32(const void* p) {
    uint32_t a;
    asm("{ .reg .u64 t; cvta.to.shared.u64 t, %1; cvt.u32.u64 %0, t; }" : "=r"(a) : "l"(p));
    return a;
}
__device__ __forceinline__ uint32_t h2_as_u32(__half2 h) {
    union { __half2 h2; uint32_t u; } cvt;
    cvt.h2 = h;
    return cvt.u;
}
__device__ __forceinline__ __half2 u32_as_h2(uint32_t u) {
    union { uint32_t u; __half2 h2; } cvt;
    cvt.u = u;
    return cvt.h2;
}
__device__ __forceinline__ void cp16(uint32_t dst, const void* src) {
    asm volatile("cp.async.cg.shared.global [%0], [%1], 16;" :: "r"(dst), "l"(src));
}
__device__ __forceinline__ void cp_commit() { asm volatile("cp.async.commit_group;" ::: "memory"); }
template <int N> __device__ __forceinline__ void cp_wait() { asm volatile("cp.async.wait_group %0;" :: "n"(N) : "memory"); }

#define LDSM_X4(r0, r1, r2, r3, addr) \
    asm volatile("ldmatrix.sync.aligned.m8n8.x4.shared.b16 {%0,%1,%2,%3}, [%4];" \
        : "=r"(r0), "=r"(r1), "=r"(r2), "=r"(r3) : "r"(addr))
#define LDSM_X4_T(r0, r1, r2, r3, addr) \
    asm volatile("ldmatrix.sync.aligned.m8n8.x4.trans.shared.b16 {%0,%1,%2,%3}, [%4];" \
        : "=r"(r0), "=r"(r1), "=r"(r2), "=r"(r3) : "r"(addr))

#define MMA16816(d, a0, a1, a2, a3, b0, b1) \
    asm volatile("mma.sync.aligned.m16n8k16.row.col.f32.f16.f16.f32 " \
        "{%0,%1,%2,%3},{%4,%5,%6,%7},{%8,%9},{%0,%1,%2,%3};" \
        : "+f"((d)[0]), "+f"((d)[1]), "+f"((d)[2]), "+f"((d)[3]) \
        : "r"(a0), "r"(a1), "r"(a2), "r"(a3), "r"(b0), "r"(b1))

#define SMEM_SWZ(off)    ((off) ^ (((off) >> 3) & 0x70))   // 128B rows
#define SMEM_SWZ256(off) ((off) ^ (((off) >> 4) & 0x70))   // 256B rows

// ==================== prep kernels ====================
__global__ void __launch_bounds__(256) convert_h_kernel(const float* __restrict__ in,
                                                        __half* __restrict__ out) {
    const size_t i = (size_t)blockIdx.x * 256 + threadIdx.x;
    float4 v = ((const float4*)in)[i];
    __half2* op = (__half2*)out;
    op[2 * i]     = __floats2half2_rn(v.x, v.y);
    op[2 * i + 1] = __floats2half2_rn(v.z, v.w);
}

// W: [K,N] fp32 -> [N,K] fp16, half2 stores. block (32,8), tile 64k x 32n.
__global__ void __launch_bounds__(256) splitT_kernel(const float* __restrict__ in,
                                                     __half* __restrict__ outT, int K, int N) {
    __shared__ float t[64][33];
    const int n0 = blockIdx.x * 32, k0 = blockIdx.y * 64;
    const int tx = threadIdx.x, ty = threadIdx.y;
    #pragma unroll
    for (int i = ty; i < 64; i += 8)
        t[i][tx] = in[(size_t)(k0 + i) * N + n0 + tx];
    __syncthreads();
    #pragma unroll
    for (int i = ty; i < 32; i += 8) {
        const __half2 hv = __floats2half2_rn(t[tx * 2][i], t[tx * 2 + 1][i]);
        *(__half2*)(outT + (size_t)(n0 + i) * K + k0 + tx * 2) = hv;
    }
}

// ==================== HMMA GEMM (CTA 128x128, warp 64x32, 2 CTAs/SM) ====================
#define STG_BYTES 32768          // 16KB A + 16KB B
#define GEMM_SMEM (3 * STG_BYTES)

__device__ __forceinline__ void gemm_load_stage(
    const __half* __restrict__ A, const __half* __restrict__ Bt,
    int bm, int bn, int K, int kk, uint32_t stg, int tid)
{
    #pragma unroll
    for (int i = 0; i < 4; i++) {
        const int ch = tid + i * 256;
        const int r = ch >> 3, cc = ch & 7;
        cp16(stg + SMEM_SWZ((uint32_t)(r * 128 + cc * 16)),
             A + (size_t)(bm + r) * K + kk + cc * 8);
    }
    #pragma unroll
    for (int i = 0; i < 4; i++) {
        const int ch = tid + i * 256;
        const int r = ch >> 3, cc = ch & 7;
        cp16(stg + 16384 + SMEM_SWZ((uint32_t)(r * 128 + cc * 16)),
             Bt + (size_t)(bn + r) * K + kk + cc * 8);
    }
}

__device__ __forceinline__ void store_qkv_elem(int row, int col, float a, float b,
                                               float* __restrict__ outK, float* __restrict__ outV) {
    const int bb = row >> 10, s = row & 1023;
    const int seg = col >> 12, w = col & 4095;
    const int h = w >> 7, dd = w & 127;
    const int bh = bb * 32 + h;
    const __half2 hh = __floats2half2_rn(a, b);
    const size_t i16 = ((size_t)bh * 1024 + s) * 128 + dd;
    if (seg == 0) {
        *(__half2*)(g_qh + i16) = hh;
    } else if (seg == 1) {
        *(float2*)(outK + ((size_t)bh * 2048 + s) * 128 + dd) = float2{a, b};
        *(__half2*)(g_kh + i16) = hh;
    } else {
        *(float2*)(outV + ((size_t)bh * 2048 + s) * 128 + dd) = float2{a, b};
        *(__half2*)(g_vh + i16) = hh;
    }
}

template <int MODE>
__global__ void __launch_bounds__(256, 2) gemm_hmma(
    const __half* __restrict__ A, const __half* __restrict__ Bt,
    const float* __restrict__ bias, int N, int K,
    float* __restrict__ out0, float* __restrict__ outK, float* __restrict__ outV)
{
    extern __shared__ char smem[];
    const uint32_t sb = smem_u32(smem);
    const int tid = threadIdx.x;
    const int bm = blockIdx.x * 128;
    const int bn = blockIdx.y * 128;
    const int wid = tid >> 5, lane = tid & 31;
    const int wm = (wid & 1) * 64;
    const int wn = (wid >> 1) * 32;

    const int arow = wm + (lane & 15);
    const int achb = lane >> 4;
    const int brow = wn + (lane & 7) + ((lane & 16) >> 1);
    const int bchb = (lane >> 3) & 1;

    float acc[4][4][4];
    #pragma unroll
    for (int i = 0; i < 4; i++)
        #pragma unroll
        for (int j = 0; j < 4; j++)
            #pragma unroll
            for (int e = 0; e < 4; e++) acc[i][j][e] = 0.f;

    const int T = K >> 6;

    #pragma unroll
    for (int s = 0; s < 2; s++) {
        gemm_load_stage(A, Bt, bm, bn, K, s * 64, sb + s * STG_BYTES, tid);
        cp_commit();
    }

    for (int kt = 0; kt < T; kt++) {
        if (kt < T - 2) cp_wait<1>(); else cp_wait<0>();
        __syncthreads();

        if (kt + 2 < T) {
            gemm_load_stage(A, Bt, bm, bn, K, (kt + 2) * 64,
                            sb + ((kt + 2) % 3) * STG_BYTES, tid);
            cp_commit();
        }

        const uint32_t stg = sb + (kt % 3) * STG_BYTES;
        const uint32_t Ab = stg, Bb = stg + 16384;

        #pragma unroll
        for (int ks = 0; ks < 4; ks++) {
            uint32_t bfr[4][2];
            #pragma unroll
            for (int j2 = 0; j2 < 2; j2++) {
                const int rr = brow + j2 * 16;
                const int ch = (ks * 2 + bchb) ^ (rr & 7);
                uint32_t r0, r1, r2, r3;
                LDSM_X4(r0, r1, r2, r3, Bb + (uint32_t)(rr * 128 + ch * 16));
                bfr[j2 * 2 + 0][0] = r0; bfr[j2 * 2 + 0][1] = r1;
                bfr[j2 * 2 + 1][0] = r2; bfr[j2 * 2 + 1][1] = r3;
            }
            #pragma unroll
            for (int i = 0; i < 4; i++) {
                const int rr = arow + i * 16;
                const int ch = (ks * 2 + achb) ^ (rr & 7);
                uint32_t a0, a1, a2, a3;
                LDSM_X4(a0, a1, a2, a3, Ab + (uint32_t)(rr * 128 + ch * 16));
                #pragma unroll
                for (int j = 0; j < 4; j++)
                    MMA16816(acc[i][j], a0, a1, a2, a3, bfr[j][0], bfr[j][1]);
            }
        }
    }

    // epilogue
    const int lr = lane >> 2, lc2 = (lane & 3) * 2;
    #pragma unroll
    for (int i = 0; i < 4; i++) {
        #pragma unroll
        for (int j = 0; j < 4; j++) {
            const int c = bn + wn + j * 8 + lc2;
            const float bx = __ldg(bias + c);
            const float by = __ldg(bias + c + 1);
            const int r0 = bm + wm + i * 16 + lr;
            const float v0 = acc[i][j][0] + bx, v1 = acc[i][j][1] + by;
            const float v2 = acc[i][j][2] + bx, v3 = acc[i][j][3] + by;
            if (MODE == 0) {
                *(float2*)(out0 + (size_t)r0 * N + c) = float2{v0, v1};
                *(float2*)(out0 + (size_t)(r0 + 8) * N + c) = float2{v2, v3};
            } else {
                store_qkv_elem(r0, c, v0, v1, outK, outV);
                store_qkv_elem(r0 + 8, c, v2, v3, outK, outV);
            }
        }
    }
}

// ==================== HMMA flash attention (64 q-rows, 4 warps, 3 CTAs/SM) ====================
// QK = qh*kh ; PV = ph*vh (denominator from rounded ph). Calibrated error model.
// Operand-phased single buffers: K(t+1) loads during softmax/PV; V(t+1) during next QK.
#define ATT_QH 0
#define ATT_KH 16384
#define ATT_VH 32768
#define ATT_SMEM 49152

__device__ __forceinline__ void attn_load_tile128(uint32_t dst, const __half* __restrict__ src,
                                                  int tid) {
    // 64 rows x 128 halves (256B rows, swizzled), 128 threads
    #pragma unroll
    for (int i = 0; i < 8; i++) {
        const int ch = tid + i * 128;
        const int r = ch >> 4, c = ch & 15;
        cp16(dst + SMEM_SWZ256((uint32_t)(r * 256 + c * 16)), src + (size_t)r * 128 + c * 8);
    }
}

__global__ void __launch_bounds__(128, 3) attn_hmma()
{
    extern __shared__ char smem[];
    const uint32_t sb = smem_u32(smem);
    const int qt = (int)gridDim.x - 1 - (int)blockIdx.x;   // longest-first schedule
    const int bh = blockIdx.y;
    const int b = bh >> 5, h = bh & 31;
    const int tid = threadIdx.x;
    const int wid = tid >> 5, lane = tid & 31;

    // Q tile
    const size_t qoff = ((size_t)bh * 1024 + qt * 64) * 128;
    attn_load_tile128(sb + ATT_QH, g_qh + qoff, tid);
    cp_commit();

    const int nkt = qt + 1;
    const size_t kvbase = (size_t)bh * 1024 * 128;

    // prologue: K0, V0
    attn_load_tile128(sb + ATT_KH, g_kh + kvbase, tid);
    cp_commit();
    attn_load_tile128(sb + ATT_VH, g_vh + kvbase, tid);
    cp_commit();

    float o[16][4];
    #pragma unroll
    for (int nt = 0; nt < 16; nt++)
        #pragma unroll
        for (int e = 0; e < 4; e++) o[nt][e] = 0.f;
    float m1 = -INFINITY, m2 = -INFINITY, l1 = 0.f, l2 = 0.f;
    const float scale2 = 0.08838834764831845f * 1.4426950408889634f;  // scale*log2(e)

    const int row1 = qt * 64 + wid * 16 + (lane >> 2);
    const int row2 = row1 + 8;

    const int qar = wid * 16 + (lane & 15);
    const int qchb = lane >> 4;
    const int kbr = (lane & 7) + ((lane & 16) >> 1);
    const int kchb = (lane >> 3) & 1;
    const int vkv = lane & 15;
    const int vdc = lane >> 4;

    for (int kt = 0; kt < nkt; kt++) {
        // wait: Q + K_kt complete (V_kt may still be in flight)
        cp_wait<1>();
        __syncthreads();

        float s[8][4];
        #pragma unroll
        for (int nt = 0; nt < 8; nt++)
            #pragma unroll
            for (int e = 0; e < 4; e++) s[nt][e] = 0.f;

        // QK: qh * kh (single pass)
        #pragma unroll
        for (int ks = 0; ks < 8; ks++) {
            uint32_t bfr[8][2];
            #pragma unroll
            for (int j2 = 0; j2 < 4; j2++) {
                const int rr = kbr + j2 * 16;
                const int ch = (ks * 2 + kchb) ^ (lane & 7);
                uint32_t r0, r1, r2, r3;
                LDSM_X4(r0, r1, r2, r3, sb + ATT_KH + (uint32_t)(rr * 256 + ch * 16));
                bfr[j2 * 2][0] = r0; bfr[j2 * 2][1] = r1;
                bfr[j2 * 2 + 1][0] = r2; bfr[j2 * 2 + 1][1] = r3;
            }
            const int ch = (ks * 2 + qchb) ^ (qar & 7);
            uint32_t a0, a1, a2, a3;
            LDSM_X4(a0, a1, a2, a3, sb + ATT_QH + (uint32_t)(qar * 256 + ch * 16));
            #pragma unroll
            for (int j = 0; j < 8; j++) MMA16816(s[j], a0, a1, a2, a3, bfr[j][0], bfr[j][1]);
        }

        // K buffer free -> start K(t+1) load
        __syncthreads();
        if (kt + 1 < nkt) {
            attn_load_tile128(sb + ATT_KH, g_kh + kvbase + (size_t)(kt + 1) * 64 * 128, tid);
            cp_commit();
        }

        // scale (base-2) + mask (diagonal tile only) + online softmax
        const bool need_mask = (kt == qt);
        float mx1 = -INFINITY, mx2 = -INFINITY;
        #pragma unroll
        for (int nt = 0; nt < 8; nt++) {
            const int cg = kt * 64 + nt * 8 + (lane & 3) * 2;
            #pragma unroll
            for (int e = 0; e < 2; e++) {
                float v = s[nt][e] * scale2;
                if (need_mask && (cg + e > row1)) v = -INFINITY;
                s[nt][e] = v; mx1 = fmaxf(mx1, v);
            }
            #pragma unroll
            for (int e = 2; e < 4; e++) {
                float v = s[nt][e] * scale2;
                if (need_mask && (cg + e - 2 > row2)) v = -INFINITY;
                s[nt][e] = v; mx2 = fmaxf(mx2, v);
            }
        }
        mx1 = fmaxf(mx1, __shfl_xor_sync(0xffffffffu, mx1, 1));
        mx1 = fmaxf(mx1, __shfl_xor_sync(0xffffffffu, mx1, 2));
        mx2 = fmaxf(mx2, __shfl_xor_sync(0xffffffffu, mx2, 1));
        mx2 = fmaxf(mx2, __shfl_xor_sync(0xffffffffu, mx2, 2));
        const float mn1 = fmaxf(m1, mx1), mn2 = fmaxf(m2, mx2);
        const float c1 = exp2f(m1 - mn1), c2 = exp2f(m2 - mn2);
        m1 = mn1; m2 = mn2;

        uint32_t ph2[8][2];
        float ts1 = 0.f, ts2 = 0.f;
        #pragma unroll
        for (int nt = 0; nt < 8; nt++) {
            const uint32_t u1 = h2_as_u32(__floats2half2_rn(s[nt][0] - mn1, s[nt][1] - mn1));
            const uint32_t u2 = h2_as_u32(__floats2half2_rn(s[nt][2] - mn2, s[nt][3] - mn2));
            uint32_t r1u, r2u;
            asm("ex2.approx.f16x2 %0, %1;" : "=r"(r1u) : "r"(u1));
            asm("ex2.approx.f16x2 %0, %1;" : "=r"(r2u) : "r"(u2));
            ph2[nt][0] = r1u; ph2[nt][1] = r2u;
            const float2 f1 = __half22float2(u32_as_h2(r1u));
            const float2 f2 = __half22float2(u32_as_h2(r2u));
            ts1 += f1.x + f1.y;
            ts2 += f2.x + f2.y;
        }
        l1 = l1 * c1 + ts1; l2 = l2 * c2 + ts2;
        #pragma unroll
        for (int nt = 0; nt < 16; nt++) {
            o[nt][0] *= c1; o[nt][1] *= c1; o[nt][2] *= c2; o[nt][3] *= c2;
        }

        // wait: V_kt complete (K(t+1) may be pending)
        if (kt + 1 < nkt) cp_wait<1>(); else cp_wait<0>();
        __syncthreads();

        // PV: ph * vh
        #pragma unroll
        for (int ks = 0; ks < 4; ks++) {
            const uint32_t ah0 = ph2[2 * ks][0], ah1 = ph2[2 * ks][1];
            const uint32_t ah2 = ph2[2 * ks + 1][0], ah3 = ph2[2 * ks + 1][1];
            #pragma unroll
            for (int d2 = 0; d2 < 8; d2++) {
                const int kvr = ks * 16 + vkv;
                const int ch = (d2 * 2 + vdc) ^ (vkv & 7);
                const uint32_t va = (uint32_t)(kvr * 256 + ch * 16);
                uint32_t v0, v1, v2, v3;
                LDSM_X4_T(v0, v1, v2, v3, sb + ATT_VH + va);
                MMA16816(o[2 * d2],     ah0, ah1, ah2, ah3, v0, v1);
                MMA16816(o[2 * d2 + 1], ah0, ah1, ah2, ah3, v2, v3);
            }
        }

        // V buffer free -> start V(t+1) load
        __syncthreads();
        if (kt + 1 < nkt) {
            attn_load_tile128(sb + ATT_VH, g_vh + kvbase + (size_t)(kt + 1) * 64 * 128, tid);
            cp_commit();
        }
    }

    l1 += __shfl_xor_sync(0xffffffffu, l1, 1);
    l1 += __shfl_xor_sync(0xffffffffu, l1, 2);
    l2 += __shfl_xor_sync(0xffffffffu, l2, 1);
    l2 += __shfl_xor_sync(0xffffffffu, l2, 2);
    const float i1 = 1.f / l1, i2 = 1.f / l2;

    __half* outp = g_aout_h;
    #pragma unroll
    for (int nt = 0; nt < 16; nt++) {
        const int col = h * 128 + nt * 8 + (lane & 3) * 2;
        *(__half2*)(outp + (size_t)(b * 1024 + row1) * 4096 + col) =
            __floats2half2_rn(o[nt][0] * i1, o[nt][1] * i1);
        *(__half2*)(outp + (size_t)(b * 1024 + row2) * 4096 + col) =
            __floats2half2_rn(o[nt][2] * i2, o[nt][3] * i2);
    }
}

// ==================== launch ====================
extern "C" void kernel_launch(void* const* d_in, const int* in_sizes, int n_in,
                              void* d_out, int out_size)
{
    const float* x       = (const float*)d_in[0];
    const float* W_qkv   = (const float*)d_in[2];
    const float* b_qkv   = (const float*)d_in[3];
    const float* W_out   = (const float*)d_in[4];
    const float* b_out   = (const float*)d_in[5];
    const float* cache_k = (const float*)d_in[6];
    const float* cache_v = (const float*)d_in[7];

    float* out  = (float*)d_out;
    float* y    = out;
    float* outK = out + 8388608;
    float* outV = out + 25165824;

    __half *ah, *aout, *bq, *wo;
    cudaGetSymbolAddress((void**)&ah, g_ah);
    cudaGetSymbolAddress((void**)&aout, g_aout_h);
    cudaGetSymbolAddress((void**)&bq, g_bqkv);
    cudaGetSymbolAddress((void**)&wo, g_wout);

    // one-time side-stream + fork/join events (no device memory involved)
    static cudaStream_t s1 = nullptr;
    static cudaEvent_t evFork = nullptr, evConv = nullptr, evPrep = nullptr, evBq = nullptr;
    if (s1 == nullptr) {
        cudaStreamCreateWithFlags(&s1, cudaStreamNonBlocking);
        cudaEventCreateWithFlags(&evFork, cudaEventDisableTiming);
        cudaEventCreateWithFlags(&evConv, cudaEventDisableTiming);
        cudaEventCreateWithFlags(&evPrep, cudaEventDisableTiming);
        cudaEventCreateWithFlags(&evBq, cudaEventDisableTiming);
    }

    cudaFuncSetAttribute(gemm_hmma<0>, cudaFuncAttributeMaxDynamicSharedMemorySize, GEMM_SMEM);
    cudaFuncSetAttribute(gemm_hmma<1>, cudaFuncAttributeMaxDynamicSharedMemorySize, GEMM_SMEM);
    cudaFuncSetAttribute(attn_hmma, cudaFuncAttributeMaxDynamicSharedMemorySize, ATT_SMEM);

    // ---- fork side stream ----
    cudaEventRecord(evFork, 0);
    cudaStreamWaitEvent(s1, evFork, 0);

    // side stream phase 1: ONLY the QKV prerequisite (x -> fp16).
    convert_h_kernel<<<8192, 256, 0, s1>>>(x, ah);
    cudaEventRecord(evConv, s1);

    // main stream: W_qkv transpose (the other QKV prerequisite)
    splitT_kernel<<<dim3(384, 64), dim3(32, 8)>>>(W_qkv, bq, 4096, 12288);
    cudaEventRecord(evBq, 0);

    // side stream phase 2: deferred until W_qkv transpose done, so the cache
    // copies + W_out transpose run UNDER the QKV GEMM (DRAM there is ~5% busy)
    // instead of competing for bandwidth in the pre-QKV window.
    cudaStreamWaitEvent(s1, evBq, 0);
    {
        const size_t pitch = (size_t)2048 * 128 * sizeof(float);
        const size_t width = (size_t)1024 * 128 * sizeof(float);
        cudaMemcpy2DAsync(outK + (size_t)1024 * 128, pitch,
                          cache_k + (size_t)1024 * 128, pitch, width, 64,
                          cudaMemcpyDeviceToDevice, s1);
        cudaMemcpy2DAsync(outV + (size_t)1024 * 128, pitch,
                          cache_v + (size_t)1024 * 128, pitch, width, 64,
                          cudaMemcpyDeviceToDevice, s1);
    }
    splitT_kernel<<<dim3(128, 64), dim3(32, 8), 0, s1>>>(W_out, wo, 4096, 4096);
    cudaEventRecord(evPrep, s1);

    // QKV GEMM needs g_ah (side stream) + g_bqkv (this stream)
    cudaStreamWaitEvent(0, evConv, 0);
    gemm_hmma<1><<<dim3(16, 96), 256, GEMM_SMEM>>>(ah, bq, b_qkv, 12288, 4096,
                                                   nullptr, outK, outV);

    attn_hmma<<<dim3(16, 64), 128, ATT_SMEM>>>();

    // out-proj needs g_wout; evPrep also covers cache-copy completion
    cudaStreamWaitEvent(0, evPrep, 0);
    gemm_hmma<0><<<dim3(16, 32), 256, GEMM_SMEM>>>(aout, wo, b_out, 4096, 4096,
                                                   y, nullptr, nullptr);
}